// round 1
// baseline (speedup 1.0000x reference)
#include <cuda_runtime.h>

// Problem constants (fixed shapes)
#define NB   2
#define NT   16
#define NN   10000
#define NIN  128
#define NHID 256
#define NOUT 128
#define NE   160000

#define ROWS (NB*NN)          // 20000
#define KCAT 384              // 128 (x-agg) + 256 (h-agg)
#define GC   1024             // [r | z | xn | hn] each 256

// ---------------- device scratch (static, no allocations) ----------------
__device__ float g_Acat[(size_t)ROWS * KCAT];       // 30.7 MB
__device__ float g_G[(size_t)ROWS * GC];            // 81.9 MB
__device__ float g_h[(size_t)ROWS * NHID];          // 20.5 MB
__device__ float g_Wpack[KCAT * GC];                // 1.57 MB
__device__ float g_biasPack[GC];
__device__ int   g_rowptr[NN + 1];
__device__ int   g_counts[NN];
__device__ int   g_fill[NN];
__device__ float g_dinv[NN];
__device__ int   g_col[NE];
__device__ float g_wedge[NE];

// ---------------- sparse setup kernels ----------------
__global__ void k_zero_counts() {
    int i = blockIdx.x * blockDim.x + threadIdx.x;
    if (i < NN) g_counts[i] = 0;
}

__global__ void k_count(const int* __restrict__ ei) {
    int e = blockIdx.x * blockDim.x + threadIdx.x;
    if (e < NE) atomicAdd(&g_counts[ei[NE + e]], 1);   // dst row
}

__global__ void k_dinv() {
    int i = blockIdx.x * blockDim.x + threadIdx.x;
    if (i < NN) g_dinv[i] = rsqrtf((float)g_counts[i] + 1.0f);  // +1 self loop
}

// single-block exclusive scan of g_counts -> g_rowptr
__global__ void k_scan() {
    __shared__ int ssum[1024];
    int tid = threadIdx.x;
    const int CH = (NN + 1023) / 1024;   // 10
    int start = tid * CH;
    int s = 0;
    for (int i = 0; i < CH; i++) {
        int idx = start + i;
        if (idx < NN) s += g_counts[idx];
    }
    ssum[tid] = s;
    __syncthreads();
    for (int off = 1; off < 1024; off <<= 1) {
        int v = 0;
        if (tid >= off) v = ssum[tid - off];
        __syncthreads();
        ssum[tid] += v;
        __syncthreads();
    }
    int run = ssum[tid] - s;   // exclusive prefix
    for (int i = 0; i < CH; i++) {
        int idx = start + i;
        if (idx < NN) {
            g_rowptr[idx] = run;
            run += g_counts[idx];
        }
    }
    if (tid == 1023) g_rowptr[NN] = ssum[1023];
}

__global__ void k_fillinit() {
    int i = blockIdx.x * blockDim.x + threadIdx.x;
    if (i < NN) g_fill[i] = g_rowptr[i];
}

__global__ void k_scatter(const int* __restrict__ ei) {
    int e = blockIdx.x * blockDim.x + threadIdx.x;
    if (e < NE) {
        int s = ei[e];
        int d = ei[NE + e];
        int pos = atomicAdd(&g_fill[d], 1);
        g_col[pos]   = s;
        g_wedge[pos] = g_dinv[s] * g_dinv[d];
    }
}

__global__ void k_zero_h() {
    int i = blockIdx.x * blockDim.x + threadIdx.x;
    if (i < ROWS * NHID) g_h[i] = 0.0f;
}

// ---------------- weight packing ----------------
// Wpack[384][1024]: cols 0-255 = [Wxr; Whr], 256-511 = [Wxz; Whz],
//                   512-767 = [Wxn; 0], 768-1023 = [0; Whn]
__global__ void k_pack(const float* __restrict__ Wxr, const float* __restrict__ Whr,
                       const float* __restrict__ Wxz, const float* __restrict__ Whz,
                       const float* __restrict__ Wxn, const float* __restrict__ Whn,
                       const float* __restrict__ bxr, const float* __restrict__ bhr,
                       const float* __restrict__ bxz, const float* __restrict__ bhz,
                       const float* __restrict__ bxn, const float* __restrict__ bhn) {
    int idx = blockIdx.x * blockDim.x + threadIdx.x;
    if (idx < KCAT * GC) {
        int k = idx >> 10;          // 0..383
        int c = idx & 1023;         // 0..1023
        float v = 0.0f;
        if (c < 256) {
            v = (k < 128) ? Wxr[k * 256 + c] : Whr[(k - 128) * 256 + c];
        } else if (c < 512) {
            int cc = c - 256;
            v = (k < 128) ? Wxz[k * 256 + cc] : Whz[(k - 128) * 256 + cc];
        } else if (c < 768) {
            int cc = c - 512;
            v = (k < 128) ? Wxn[k * 256 + cc] : 0.0f;
        } else {
            int cc = c - 768;
            v = (k < 128) ? 0.0f : Whn[(k - 128) * 256 + cc];
        }
        g_Wpack[idx] = v;
    }
    if (idx < GC) {
        float bv;
        if (idx < 256)      bv = bxr[idx] + bhr[idx];
        else if (idx < 512) bv = bxz[idx - 256] + bhz[idx - 256];
        else if (idx < 768) bv = bxn[idx - 512];
        else                bv = bhn[idx - 768];
        g_biasPack[idx] = bv;
    }
}

// ---------------- GCN aggregation (CSR gather) ----------------
// out[b, node, d] = dinv[node]^2 * in[b, node, d] + sum_j w[j] * in[b, col[j], d]
__global__ void k_agg(const float* __restrict__ vin, long long bs_in, int ld_in,
                      float* __restrict__ vout, long long bs_out, int ld_out) {
    int node = blockIdx.x;
    int b    = blockIdx.y;
    int d    = threadIdx.x;
    const float* vi = vin + (size_t)b * bs_in;
    float di = g_dinv[node];
    float acc = di * di * vi[(size_t)node * ld_in + d];
    int beg = g_rowptr[node], end = g_rowptr[node + 1];
    for (int j = beg; j < end; ++j) {
        acc += g_wedge[j] * vi[(size_t)g_col[j] * ld_in + d];
    }
    vout[(size_t)b * bs_out + (size_t)node * ld_out + d] = acc;
}

// ---------------- SGEMM: C = A @ B + bias ----------------
// BM=128, BN=128, BK=8, 256 threads, 8x8 per thread (split-N fragments)
template <bool SCATTER>
__global__ void __launch_bounds__(256)
k_sgemm(const float* __restrict__ A, int lda,
        const float* __restrict__ B, int ldb,
        float* __restrict__ C, int ldc,
        const float* __restrict__ bias,
        int M, int K, int t) {
    __shared__ __align__(16) float As[8][128];
    __shared__ __align__(16) float Bs[8][128];

    int tid = threadIdx.x;
    int ty = tid >> 4;          // 0..15
    int tx = tid & 15;          // 0..15
    int m0 = blockIdx.y * 128;
    int n0 = blockIdx.x * 128;

    int a_row = tid >> 1;               // 0..127
    int a_c4  = (tid & 1) * 4;          // 0 or 4
    int b_row = tid >> 5;               // 0..7
    int b_col = (tid & 31) * 4;         // 0..124

    float acc[8][8];
#pragma unroll
    for (int i = 0; i < 8; i++)
#pragma unroll
        for (int j = 0; j < 8; j++) acc[i][j] = 0.0f;

    for (int k0 = 0; k0 < K; k0 += 8) {
        float4 av;
        int gr = m0 + a_row;
        if (gr < M) av = *(const float4*)&A[(size_t)gr * lda + k0 + a_c4];
        else        av = make_float4(0.f, 0.f, 0.f, 0.f);
        As[a_c4 + 0][a_row] = av.x;
        As[a_c4 + 1][a_row] = av.y;
        As[a_c4 + 2][a_row] = av.z;
        As[a_c4 + 3][a_row] = av.w;

        float4 bv = *(const float4*)&B[(size_t)(k0 + b_row) * ldb + n0 + b_col];
        *(float4*)&Bs[b_row][b_col] = bv;

        __syncthreads();
#pragma unroll
        for (int k = 0; k < 8; k++) {
            float a[8], b[8];
            float4 ta0 = *(const float4*)&As[k][ty * 4];
            float4 ta1 = *(const float4*)&As[k][64 + ty * 4];
            float4 tb0 = *(const float4*)&Bs[k][tx * 4];
            float4 tb1 = *(const float4*)&Bs[k][64 + tx * 4];
            a[0] = ta0.x; a[1] = ta0.y; a[2] = ta0.z; a[3] = ta0.w;
            a[4] = ta1.x; a[5] = ta1.y; a[6] = ta1.z; a[7] = ta1.w;
            b[0] = tb0.x; b[1] = tb0.y; b[2] = tb0.z; b[3] = tb0.w;
            b[4] = tb1.x; b[5] = tb1.y; b[6] = tb1.z; b[7] = tb1.w;
#pragma unroll
            for (int i = 0; i < 8; i++)
#pragma unroll
                for (int j = 0; j < 8; j++) acc[i][j] += a[i] * b[j];
        }
        __syncthreads();
    }

#pragma unroll
    for (int i = 0; i < 8; i++) {
        int lr = (i < 4) ? (ty * 4 + i) : (64 + ty * 4 + i - 4);
        int gr = m0 + lr;
        if (gr >= M) continue;
#pragma unroll
        for (int j = 0; j < 8; j++) {
            int lc = (j < 4) ? (tx * 4 + j) : (64 + tx * 4 + j - 4);
            int gc = n0 + lc;
            float v = acc[i][j] + bias[gc];
            if (SCATTER) {
                int bb = gr / NN;
                int nn = gr - bb * NN;
                C[(((size_t)bb * NT + t) * NN + nn) * NOUT + gc] = v;
            } else {
                C[(size_t)gr * ldc + gc] = v;
            }
        }
    }
}

// ---------------- fused GRU elementwise ----------------
__global__ void k_gru() {
    int idx = blockIdx.x * blockDim.x + threadIdx.x;
    if (idx >= ROWS * NHID) return;
    int row = idx >> 8;          // NHID = 256
    int d   = idx & 255;
    const float* g = g_G + (size_t)row * GC;
    float rp = g[d];
    float zp = g[256 + d];
    float xn = g[512 + d];
    float hn = g[768 + d];
    float r = 1.0f / (1.0f + __expf(-rp));
    float z = 1.0f / (1.0f + __expf(-zp));
    float n = tanhf(xn + r * hn);
    float h = g_h[idx];
    g_h[idx] = (1.0f - z) * h + z * n;
}

// ---------------- launcher ----------------
extern "C" void kernel_launch(void* const* d_in, const int* in_sizes, int n_in,
                              void* d_out, int out_size) {
    (void)in_sizes; (void)n_in; (void)out_size;
    const float* x   = (const float*)d_in[0];
    const int*   ei  = (const int*)d_in[1];
    const float* Wxr = (const float*)d_in[2];  const float* bxr = (const float*)d_in[3];
    const float* Whr = (const float*)d_in[4];  const float* bhr = (const float*)d_in[5];
    const float* Wxz = (const float*)d_in[6];  const float* bxz = (const float*)d_in[7];
    const float* Whz = (const float*)d_in[8];  const float* bhz = (const float*)d_in[9];
    const float* Wxn = (const float*)d_in[10]; const float* bxn = (const float*)d_in[11];
    const float* Whn = (const float*)d_in[12]; const float* bhn = (const float*)d_in[13];
    const float* Wfc = (const float*)d_in[14]; const float* bfc = (const float*)d_in[15];
    float* out = (float*)d_out;

    float *pAcat, *pG, *ph, *pWpack, *pbias;
    cudaGetSymbolAddress((void**)&pAcat,  g_Acat);
    cudaGetSymbolAddress((void**)&pG,     g_G);
    cudaGetSymbolAddress((void**)&ph,     g_h);
    cudaGetSymbolAddress((void**)&pWpack, g_Wpack);
    cudaGetSymbolAddress((void**)&pbias,  g_biasPack);

    // sparse setup (deterministic every call)
    k_zero_counts<<<(NN + 255) / 256, 256>>>();
    k_count<<<(NE + 255) / 256, 256>>>(ei);
    k_dinv<<<(NN + 255) / 256, 256>>>();
    k_scan<<<1, 1024>>>();
    k_fillinit<<<(NN + 255) / 256, 256>>>();
    k_scatter<<<(NE + 255) / 256, 256>>>(ei);
    k_pack<<<(KCAT * GC + 255) / 256, 256>>>(Wxr, Whr, Wxz, Whz, Wxn, Whn,
                                             bxr, bhr, bxz, bhz, bxn, bhn);
    k_zero_h<<<(ROWS * NHID + 255) / 256, 256>>>();

    dim3 stepGrid(GC / 128, (ROWS + 127) / 128);    // 8 x 157
    dim3 fcGrid(NOUT / 128, (ROWS + 127) / 128);    // 1 x 157

    for (int t = 0; t < NT; t++) {
        // Acat[:, 0:128]  = A * x_t      (per batch)
        k_agg<<<dim3(NN, NB), NIN>>>(x + (size_t)t * NN * NIN,
                                     (long long)NT * NN * NIN, NIN,
                                     pAcat, (long long)NN * KCAT, KCAT);
        // Acat[:, 128:384] = A * h
        k_agg<<<dim3(NN, NB), NHID>>>(ph, (long long)NN * NHID, NHID,
                                      pAcat + 128, (long long)NN * KCAT, KCAT);
        // G = Acat @ Wpack + biasPack  (r-pre | z-pre | xn | hn)
        k_sgemm<false><<<stepGrid, 256>>>(pAcat, KCAT, pWpack, GC, pG, GC,
                                          pbias, ROWS, KCAT, 0);
        // GRU elementwise update of h
        k_gru<<<(ROWS * NHID + 255) / 256, 256>>>();
        // out[:, t] = h @ Wfc + bfc (scatter epilogue into [B,T,N,OUT])
        k_sgemm<true><<<fcGrid, 256>>>(ph, NHID, Wfc, NOUT, out, 0,
                                       bfc, ROWS, NHID, t);
    }
}

// round 4
// speedup vs baseline: 1.6166x; 1.6166x over previous
#include <cuda_runtime.h>
#include <cuda_bf16.h>
#include <cstdint>

// Problem constants (fixed shapes)
#define NB   2
#define NT   16
#define NN   10000
#define NIN  128
#define NHID 256
#define NOUT 128
#define NE   160000

#define ROWS (NB*NN)          // 20000
#define KCAT 384              // 128 (x-agg) + 256 (h-agg)
#define GC   1024             // interleaved: col 4*d+gate, gate = r,z,xn,hn

#define BM 128
#define BN 128
#define BK 16

typedef __nv_bfloat16 bf16;

// ---------------- device scratch (static, no allocations) ----------------
__device__ bf16  g_AcatHi[(size_t)ROWS * KCAT];     // 15.4 MB
__device__ bf16  g_AcatLo[(size_t)ROWS * KCAT];
__device__ float g_h[(size_t)ROWS * NHID];          // 20.5 MB
__device__ bf16  g_hHi[(size_t)ROWS * NHID];
__device__ bf16  g_hLo[(size_t)ROWS * NHID];
__device__ bf16  g_WThi[GC * KCAT];                 // [n'][k] transposed
__device__ bf16  g_WTlo[GC * KCAT];
__device__ bf16  g_WfcThi[NOUT * NHID];             // [o][k]
__device__ bf16  g_WfcTlo[NOUT * NHID];
__device__ float g_biasPack[GC];                    // interleaved 4*d+gate
__device__ int   g_rowptr[NN + 1];
__device__ int   g_counts[NN];
__device__ int   g_fill[NN];
__device__ float g_dinv[NN];
__device__ int   g_col[NE];
__device__ float g_wedge[NE];

__device__ __forceinline__ void split2(float v, bf16& hi, bf16& lo) {
    hi = __float2bfloat16_rn(v);
    lo = __float2bfloat16_rn(v - __bfloat162float(hi));
}

// ---------------- sparse setup kernels ----------------
__global__ void k_zero_counts() {
    int i = blockIdx.x * blockDim.x + threadIdx.x;
    if (i < NN) g_counts[i] = 0;
}

__global__ void k_count(const int* __restrict__ ei) {
    int e = blockIdx.x * blockDim.x + threadIdx.x;
    if (e < NE) atomicAdd(&g_counts[ei[NE + e]], 1);   // dst row
}

__global__ void k_dinv() {
    int i = blockIdx.x * blockDim.x + threadIdx.x;
    if (i < NN) g_dinv[i] = rsqrtf((float)g_counts[i] + 1.0f);  // +1 self loop
}

// single-block exclusive scan of g_counts -> g_rowptr
__global__ void k_scan() {
    __shared__ int ssum[1024];
    int tid = threadIdx.x;
    const int CH = (NN + 1023) / 1024;   // 10
    int start = tid * CH;
    int s = 0;
    for (int i = 0; i < CH; i++) {
        int idx = start + i;
        if (idx < NN) s += g_counts[idx];
    }
    ssum[tid] = s;
    __syncthreads();
    for (int off = 1; off < 1024; off <<= 1) {
        int v = 0;
        if (tid >= off) v = ssum[tid - off];
        __syncthreads();
        ssum[tid] += v;
        __syncthreads();
    }
    int run = ssum[tid] - s;   // exclusive prefix
    for (int i = 0; i < CH; i++) {
        int idx = start + i;
        if (idx < NN) {
            g_rowptr[idx] = run;
            run += g_counts[idx];
        }
    }
    if (tid == 1023) g_rowptr[NN] = ssum[1023];
}

__global__ void k_fillinit() {
    int i = blockIdx.x * blockDim.x + threadIdx.x;
    if (i < NN) g_fill[i] = g_rowptr[i];
}

__global__ void k_scatter(const int* __restrict__ ei) {
    int e = blockIdx.x * blockDim.x + threadIdx.x;
    if (e < NE) {
        int s = ei[e];
        int d = ei[NE + e];
        int pos = atomicAdd(&g_fill[d], 1);
        g_col[pos]   = s;
        g_wedge[pos] = g_dinv[s] * g_dinv[d];
    }
}

__global__ void k_zero_h() {
    int i = blockIdx.x * blockDim.x + threadIdx.x;
    if (i < ROWS * NHID) {
        g_h[i] = 0.0f;
        g_hHi[i] = __float2bfloat16(0.0f);
        g_hLo[i] = __float2bfloat16(0.0f);
    }
}

// ---------------- weight packing (transposed + gate-interleaved + split) ----
// WT[col'][k], col' = 4*d + gate:
//   gate 0 (r):  k<128 ? Wxr[k][d] : Whr[k-128][d]
//   gate 1 (z):  k<128 ? Wxz[k][d] : Whz[k-128][d]
//   gate 2 (xn): k<128 ? Wxn[k][d] : 0
//   gate 3 (hn): k<128 ? 0         : Whn[k-128][d]
__global__ void k_pack(const float* __restrict__ Wxr, const float* __restrict__ Whr,
                       const float* __restrict__ Wxz, const float* __restrict__ Whz,
                       const float* __restrict__ Wxn, const float* __restrict__ Whn,
                       const float* __restrict__ bxr, const float* __restrict__ bhr,
                       const float* __restrict__ bxz, const float* __restrict__ bhz,
                       const float* __restrict__ bxn, const float* __restrict__ bhn,
                       const float* __restrict__ Wfc) {
    int idx = blockIdx.x * blockDim.x + threadIdx.x;
    if (idx < GC * KCAT) {
        int cp = idx / KCAT;
        int k  = idx - cp * KCAT;
        int d = cp >> 2, g = cp & 3;
        bool xk = k < 128;
        int kh = k - 128;
        float v;
        if (g == 0)      v = xk ? Wxr[k * 256 + d] : Whr[kh * 256 + d];
        else if (g == 1) v = xk ? Wxz[k * 256 + d] : Whz[kh * 256 + d];
        else if (g == 2) v = xk ? Wxn[k * 256 + d] : 0.0f;
        else             v = xk ? 0.0f : Whn[kh * 256 + d];
        bf16 hi, lo; split2(v, hi, lo);
        g_WThi[idx] = hi; g_WTlo[idx] = lo;
    }
    if (idx < GC) {
        int d = idx >> 2, g = idx & 3;
        float bv;
        if (g == 0)      bv = bxr[d] + bhr[d];
        else if (g == 1) bv = bxz[d] + bhz[d];
        else if (g == 2) bv = bxn[d];
        else             bv = bhn[d];
        g_biasPack[idx] = bv;
    }
    if (idx < NOUT * NHID) {
        int o = idx >> 8;          // NHID = 256
        int k = idx & 255;
        bf16 hi, lo; split2(Wfc[k * NOUT + o], hi, lo);
        g_WfcThi[idx] = hi; g_WfcTlo[idx] = lo;
    }
}

// ---------------- GCN aggregation (CSR gather, float4, split-bf16 out) -----
__global__ void k_agg(const float* __restrict__ vin, long long bs_in, int ld_in,
                      bf16* __restrict__ outHi, bf16* __restrict__ outLo,
                      long long bs_out, int ld_out, int col0) {
    int node = blockIdx.x;
    int b    = threadIdx.y;
    int tx   = threadIdx.x;          // feature/4
    const float* vi = vin + (size_t)b * bs_in;
    float di = g_dinv[node];
    float4 acc = *(const float4*)(vi + (size_t)node * ld_in + tx * 4);
    float sw = di * di;
    acc.x *= sw; acc.y *= sw; acc.z *= sw; acc.w *= sw;
    int beg = g_rowptr[node], end = g_rowptr[node + 1];
    for (int j = beg; j < end; ++j) {
        float w = g_wedge[j];
        int   c = g_col[j];
        float4 v = *(const float4*)(vi + (size_t)c * ld_in + tx * 4);
        acc.x += w * v.x; acc.y += w * v.y; acc.z += w * v.z; acc.w += w * v.w;
    }
    size_t o = (size_t)b * bs_out + (size_t)node * ld_out + col0 + tx * 4;
    bf16 h0, l0, h1, l1, h2, l2, h3, l3;
    split2(acc.x, h0, l0); split2(acc.y, h1, l1);
    split2(acc.z, h2, l2); split2(acc.w, h3, l3);
    ushort4 uh = make_ushort4(__bfloat16_as_ushort(h0), __bfloat16_as_ushort(h1),
                              __bfloat16_as_ushort(h2), __bfloat16_as_ushort(h3));
    ushort4 ul = make_ushort4(__bfloat16_as_ushort(l0), __bfloat16_as_ushort(l1),
                              __bfloat16_as_ushort(l2), __bfloat16_as_ushort(l3));
    *(ushort4*)(outHi + o) = uh;
    *(ushort4*)(outLo + o) = ul;
}

// ---------------- split-bf16 tensor-core GEMM ----------------
// C = A @ B with A,B given as (hi,lo) bf16 pairs; acc += AhiBhi + AhiBlo + AloBhi.
// Tiles BM=128 BN=128 BK=16; 256 threads = 8 warps (2 M x 4 N), warp 64x32,
// mma.m16n8k16.bf16.  smem layout per plane: [khalf][row][16B], plane=4KB.
// GATES=true: fused GRU epilogue updating g_h (+ bf16 splits) in place.
// GATES=false: bias + scatter store into out[B,T,N,OUT] at timestep t.

__device__ __forceinline__ uint32_t smem_u32(const void* p) {
    uint32_t a;
    asm("{ .reg .u64 t; cvta.to.shared.u64 t, %1; cvt.u32.u64 %0, t; }"
        : "=r"(a) : "l"(p));
    return a;
}

__device__ __forceinline__ void ldsm4(uint32_t& r0, uint32_t& r1, uint32_t& r2,
                                      uint32_t& r3, uint32_t addr) {
    asm volatile("ldmatrix.sync.aligned.m8n8.x4.shared.b16 {%0,%1,%2,%3}, [%4];"
                 : "=r"(r0), "=r"(r1), "=r"(r2), "=r"(r3) : "r"(addr));
}

__device__ __forceinline__ void mma16(float* c, const uint32_t* a, const uint32_t* b) {
    asm volatile(
        "mma.sync.aligned.m16n8k16.row.col.f32.bf16.bf16.f32 "
        "{%0,%1,%2,%3}, {%4,%5,%6,%7}, {%8,%9}, {%0,%1,%2,%3};"
        : "+f"(c[0]), "+f"(c[1]), "+f"(c[2]), "+f"(c[3])
        : "r"(a[0]), "r"(a[1]), "r"(a[2]), "r"(a[3]), "r"(b[0]), "r"(b[1]));
}

template <bool GATES>
__global__ void __launch_bounds__(256)
k_mma(const bf16* __restrict__ Ahi, const bf16* __restrict__ Alo, int lda,
      const bf16* __restrict__ Bhi, const bf16* __restrict__ Blo, int ldb,
      float* __restrict__ C, const float* __restrict__ bias,
      int M, int K, int t) {
    // [buf 16KB][plane 4KB: Ahi|Alo|Bhi|Blo][khalf 2KB][row][16B]
    __shared__ __align__(16) char smem[32768];

    const int tid = threadIdx.x;
    const int lane = tid & 31;
    const int wid = tid >> 5;
    const int wm = wid & 1;          // 2 warps in M
    const int wn = wid >> 1;         // 4 warps in N
    const int m0 = blockIdx.y * BM;
    const int n0 = blockIdx.x * BN;

    const uint32_t sbase = smem_u32(smem);

    // staging: thread -> (row = tid>>1, khalf = tid&1), one 16B chunk per plane
    const int st_row = tid >> 1;
    const int st_kh  = tid & 1;

    // ldmatrix lane geometry (same formula for A and B)
    const int lrow = lane & 15;
    const int lkh  = lane >> 4;

    float acc[4][4][4];
#pragma unroll
    for (int i = 0; i < 4; i++)
#pragma unroll
        for (int j = 0; j < 4; j++)
#pragma unroll
            for (int q = 0; q < 4; q++) acc[i][j][q] = 0.0f;

    const int KT = K / BK;

    auto stage = [&](int buf, int k0) {
        uint32_t base = sbase + buf * 16384u;
        uint32_t off = (uint32_t)(st_kh * 2048 + st_row * 16);
        const bf16* a_src = Ahi + (size_t)(m0 + st_row) * lda + k0 + st_kh * 8;
        const bf16* a2_src = Alo + (size_t)(m0 + st_row) * lda + k0 + st_kh * 8;
        const bf16* b_src = Bhi + (size_t)(n0 + st_row) * ldb + k0 + st_kh * 8;
        const bf16* b2_src = Blo + (size_t)(n0 + st_row) * ldb + k0 + st_kh * 8;
        int pa = ((m0 + st_row) < M) ? 16 : 0;
        asm volatile("cp.async.ca.shared.global [%0], [%1], 16, %2;"
                     :: "r"(base + off), "l"(a_src), "r"(pa));
        asm volatile("cp.async.ca.shared.global [%0], [%1], 16, %2;"
                     :: "r"(base + 4096u + off), "l"(a2_src), "r"(pa));
        asm volatile("cp.async.ca.shared.global [%0], [%1], 16, %2;"
                     :: "r"(base + 8192u + off), "l"(b_src), "r"(16));
        asm volatile("cp.async.ca.shared.global [%0], [%1], 16, %2;"
                     :: "r"(base + 12288u + off), "l"(b2_src), "r"(16));
    };

    stage(0, 0);
    asm volatile("cp.async.commit_group;");

    for (int kt = 0; kt < KT; kt++) {
        if (kt + 1 < KT) {
            stage((kt + 1) & 1, (kt + 1) * BK);
            asm volatile("cp.async.commit_group;");
            asm volatile("cp.async.wait_group 1;");
        } else {
            asm volatile("cp.async.wait_group 0;");
        }
        __syncthreads();

        const int buf = kt & 1;
        const uint32_t pA  = sbase + buf * 16384u;
        const uint32_t pA2 = pA + 4096u;
        const uint32_t pB  = pA + 8192u;
        const uint32_t pB2 = pA + 12288u;
        const uint32_t loff = (uint32_t)(lkh * 2048);

        uint32_t ah[4][4], al[4][4], bh[4][2], bl[4][2];
#pragma unroll
        for (int mt = 0; mt < 4; mt++) {
            uint32_t ro = (uint32_t)((wm * 64 + mt * 16 + lrow) * 16);
            ldsm4(ah[mt][0], ah[mt][1], ah[mt][2], ah[mt][3], pA + loff + ro);
            ldsm4(al[mt][0], al[mt][1], al[mt][2], al[mt][3], pA2 + loff + ro);
        }
#pragma unroll
        for (int j = 0; j < 2; j++) {
            uint32_t ro = (uint32_t)((wn * 32 + j * 16 + lrow) * 16);
            uint32_t r0, r1, r2, r3;
            ldsm4(r0, r1, r2, r3, pB + loff + ro);
            bh[2*j][0] = r0; bh[2*j][1] = r2;
            bh[2*j+1][0] = r1; bh[2*j+1][1] = r3;
            ldsm4(r0, r1, r2, r3, pB2 + loff + ro);
            bl[2*j][0] = r0; bl[2*j][1] = r2;
            bl[2*j+1][0] = r1; bl[2*j+1][1] = r3;
        }
#pragma unroll
        for (int mt = 0; mt < 4; mt++)
#pragma unroll
            for (int nt = 0; nt < 4; nt++) {
                mma16(acc[mt][nt], ah[mt], bh[nt]);
                mma16(acc[mt][nt], ah[mt], bl[nt]);
                mma16(acc[mt][nt], al[mt], bh[nt]);
            }
        __syncthreads();
    }

    // ---- epilogue ----
    const int gid = lane >> 2, tg = lane & 3;

    if (GATES) {
        const bool odd = lane & 1;
#pragma unroll
        for (int mt = 0; mt < 4; mt++) {
            int rowb = m0 + wm * 64 + mt * 16;
#pragma unroll
            for (int nt = 0; nt < 4; nt++) {
                float c0 = acc[mt][nt][0], c1 = acc[mt][nt][1];
                float c2 = acc[mt][nt][2], c3 = acc[mt][nt][3];
                float e0 = __shfl_xor_sync(0xffffffffu, c0, 1);
                float e1 = __shfl_xor_sync(0xffffffffu, c1, 1);
                float e2 = __shfl_xor_sync(0xffffffffu, c2, 1);
                float e3 = __shfl_xor_sync(0xffffffffu, c3, 1);
                float v0, v1, v2, v3;
                int row;
                if (!odd) { v0 = c0; v1 = c1; v2 = e0; v3 = e1; row = rowb + gid; }
                else      { v0 = e2; v1 = e3; v2 = c2; v3 = c3; row = rowb + gid + 8; }
                int d = ((n0 + wn * 32 + nt * 8) >> 2) + (tg >> 1);
                if (row < M) {
                    float4 bb = *(const float4*)&bias[4 * d];
                    float rg = 1.0f / (1.0f + __expf(-(v0 + bb.x)));
                    float zg = 1.0f / (1.0f + __expf(-(v1 + bb.y)));
                    float ng = tanhf(v2 + bb.z + rg * (v3 + bb.w));
                    size_t hoff = (size_t)row * NHID + d;
                    float h = g_h[hoff];
                    float hn2 = h + zg * (ng - h);
                    g_h[hoff] = hn2;
                    bf16 hi, lo; split2(hn2, hi, lo);
                    g_hHi[hoff] = hi;
                    g_hLo[hoff] = lo;
                }
            }
        }
    } else {
#pragma unroll
        for (int mt = 0; mt < 4; mt++) {
            int r0 = m0 + wm * 64 + mt * 16 + gid;
            int r1 = r0 + 8;
            int b0 = (r0 >= NN), b1 = (r1 >= NN);
            size_t base0 = (((size_t)b0 * NT + t) * NN + (r0 - b0 * NN)) * NOUT;
            size_t base1 = (((size_t)b1 * NT + t) * NN + (r1 - b1 * NN)) * NOUT;
#pragma unroll
            for (int nt = 0; nt < 4; nt++) {
                int col = n0 + wn * 32 + nt * 8 + tg * 2;
                float bx = bias[col], by = bias[col + 1];
                if (r0 < M) {
                    float2 o = make_float2(acc[mt][nt][0] + bx, acc[mt][nt][1] + by);
                    *(float2*)&C[base0 + col] = o;
                }
                if (r1 < M) {
                    float2 o = make_float2(acc[mt][nt][2] + bx, acc[mt][nt][3] + by);
                    *(float2*)&C[base1 + col] = o;
                }
            }
        }
    }
}

// ---------------- launcher ----------------
extern "C" void kernel_launch(void* const* d_in, const int* in_sizes, int n_in,
                              void* d_out, int out_size) {
    (void)in_sizes; (void)n_in; (void)out_size;
    const float* x   = (const float*)d_in[0];
    const int*   ei  = (const int*)d_in[1];
    const float* Wxr = (const float*)d_in[2];  const float* bxr = (const float*)d_in[3];
    const float* Whr = (const float*)d_in[4];  const float* bhr = (const float*)d_in[5];
    const float* Wxz = (const float*)d_in[6];  const float* bxz = (const float*)d_in[7];
    const float* Whz = (const float*)d_in[8];  const float* bhz = (const float*)d_in[9];
    const float* Wxn = (const float*)d_in[10]; const float* bxn = (const float*)d_in[11];
    const float* Whn = (const float*)d_in[12]; const float* bhn = (const float*)d_in[13];
    const float* Wfc = (const float*)d_in[14]; const float* bfc = (const float*)d_in[15];
    float* out = (float*)d_out;

    bf16 *pAHi, *pALo, *phHi, *phLo, *pWThi, *pWTlo, *pWfcThi, *pWfcTlo;
    float *ph, *pbias;
    cudaGetSymbolAddress((void**)&pAHi,    g_AcatHi);
    cudaGetSymbolAddress((void**)&pALo,    g_AcatLo);
    cudaGetSymbolAddress((void**)&ph,      g_h);
    cudaGetSymbolAddress((void**)&phHi,    g_hHi);
    cudaGetSymbolAddress((void**)&phLo,    g_hLo);
    cudaGetSymbolAddress((void**)&pWThi,   g_WThi);
    cudaGetSymbolAddress((void**)&pWTlo,   g_WTlo);
    cudaGetSymbolAddress((void**)&pWfcThi, g_WfcThi);
    cudaGetSymbolAddress((void**)&pWfcTlo, g_WfcTlo);
    cudaGetSymbolAddress((void**)&pbias,   g_biasPack);

    // sparse setup (deterministic every call)
    k_zero_counts<<<(NN + 255) / 256, 256>>>();
    k_count<<<(NE + 255) / 256, 256>>>(ei);
    k_dinv<<<(NN + 255) / 256, 256>>>();
    k_scan<<<1, 1024>>>();
    k_fillinit<<<(NN + 255) / 256, 256>>>();
    k_scatter<<<(NE + 255) / 256, 256>>>(ei);
    k_pack<<<(GC * KCAT + 255) / 256, 256>>>(Wxr, Whr, Wxz, Whz, Wxn, Whn,
                                             bxr, bhr, bxz, bhz, bxn, bhn, Wfc);
    k_zero_h<<<(ROWS * NHID + 255) / 256, 256>>>();

    dim3 gateGrid(GC / BN, (ROWS + BM - 1) / BM);    // 8 x 157
    dim3 fcGrid(NOUT / BN, (ROWS + BM - 1) / BM);    // 1 x 157

    for (int t = 0; t < NT; t++) {
        // Acat[:, 0:128]  = A * x_t      (per batch), split-bf16 output
        k_agg<<<NN, dim3(NIN / 4, NB)>>>(x + (size_t)t * NN * NIN,
                                         (long long)NT * NN * NIN, NIN,
                                         pAHi, pALo, (long long)NN * KCAT, KCAT, 0);
        // Acat[:, 128:384] = A * h
        k_agg<<<NN, dim3(NHID / 4, NB)>>>(ph, (long long)NN * NHID, NHID,
                                          pAHi, pALo, (long long)NN * KCAT, KCAT, 128);
        // gates GEMM + fused GRU epilogue (updates g_h + splits in place)
        k_mma<true><<<gateGrid, 256>>>(pAHi, pALo, KCAT, pWThi, pWTlo, KCAT,
                                       nullptr, pbias, ROWS, KCAT, 0);
        // out[:, t] = h_new @ Wfc + bfc (scatter epilogue)
        k_mma<false><<<fcGrid, 256>>>(phHi, phLo, NHID, pWfcThi, pWfcTlo, NHID,
                                      out, bfc, ROWS, NHID, t);
    }
}

// round 6
// speedup vs baseline: 1.7080x; 1.0565x over previous
#include <cuda_runtime.h>
#include <cuda_bf16.h>
#include <cstdint>

// Problem constants (fixed shapes)
#define NB   2
#define NT   16
#define NN   10000
#define NIN  128
#define NHID 256
#define NOUT 128
#define NE   160000

#define ROWS (NB*NN)          // 20000
#define HISTROWS (NB*NT*NN)   // 320000
#define KCAT 384              // 128 (x-agg) + 256 (h-agg)
#define GC   1024             // interleaved: col 4*d+gate, gate = r,z,xn,hn

#define BM 128
#define BN 128
#define BK 16

typedef __nv_bfloat16 bf16;

// ---------------- device scratch (static, no allocations) ----------------
__device__ bf16  g_AxHi[(size_t)HISTROWS * NIN];    // 82 MB  (A*x_t, all t)
__device__ bf16  g_AxLo[(size_t)HISTROWS * NIN];
__device__ bf16  g_AhHi[(size_t)ROWS * NHID];       // 10.2 MB (A*h, current step)
__device__ bf16  g_AhLo[(size_t)ROWS * NHID];
__device__ float g_h[(size_t)ROWS * NHID];          // 20.5 MB (fp32 h state)
__device__ bf16  g_histHi[(size_t)HISTROWS * NHID]; // 164 MB (h_t splits, all t)
__device__ bf16  g_histLo[(size_t)HISTROWS * NHID];
__device__ bf16  g_WThi[GC * KCAT];                 // [n'][k] transposed
__device__ bf16  g_WTlo[GC * KCAT];
__device__ bf16  g_WfcThi[NOUT * NHID];             // [o][k]
__device__ bf16  g_WfcTlo[NOUT * NHID];
__device__ float g_biasPack[GC];                    // interleaved 4*d+gate
__device__ int   g_rowptr[NN + 1];
__device__ int   g_counts[NN];
__device__ int   g_fill[NN];
__device__ float g_dinv[NN];
__device__ int   g_col[NE];
__device__ float g_wedge[NE];

__device__ __forceinline__ void split2(float v, bf16& hi, bf16& lo) {
    hi = __float2bfloat16_rn(v);
    lo = __float2bfloat16_rn(v - __bfloat162float(hi));
}

// ---------------- setup kernels ----------------
__global__ void k_zero_all() {
    for (int i = blockIdx.x * blockDim.x + threadIdx.x;
         i < ROWS * NHID; i += gridDim.x * blockDim.x) {
        if (i < NN) g_counts[i] = 0;
        g_h[i] = 0.0f;
    }
}

__global__ void k_count(const int* __restrict__ ei) {
    int e = blockIdx.x * blockDim.x + threadIdx.x;
    if (e < NE) atomicAdd(&g_counts[ei[NE + e]], 1);   // dst row
}

// single block: dinv + exclusive scan + fill init + CSR scatter
__global__ void k_scan_all(const int* __restrict__ ei) {
    __shared__ int ssum[1024];
    int tid = threadIdx.x;
    const int CH = (NN + 1023) / 1024;   // 10
    int start = tid * CH;
    int s = 0;
    for (int i = 0; i < CH; i++) {
        int idx = start + i;
        if (idx < NN) s += g_counts[idx];
    }
    ssum[tid] = s;
    __syncthreads();
    for (int off = 1; off < 1024; off <<= 1) {
        int v = 0;
        if (tid >= off) v = ssum[tid - off];
        __syncthreads();
        ssum[tid] += v;
        __syncthreads();
    }
    int run = ssum[tid] - s;   // exclusive prefix
    for (int i = 0; i < CH; i++) {
        int idx = start + i;
        if (idx < NN) {
            g_rowptr[idx] = run;
            g_fill[idx]   = run;
            g_dinv[idx]   = rsqrtf((float)g_counts[idx] + 1.0f);
            run += g_counts[idx];
        }
    }
    if (tid == 1023) g_rowptr[NN] = ssum[1023];
    __syncthreads();
    // scatter edges into CSR (ordering within a bucket is arbitrary; sums invariant)
    for (int e = tid; e < NE; e += 1024) {
        int sc = ei[e];
        int d  = ei[NE + e];
        int pos = atomicAdd(&g_fill[d], 1);
        g_col[pos]   = sc;
        g_wedge[pos] = g_dinv[sc] * g_dinv[d];
    }
}

// ---------------- agg(x_t) for ALL t in one launch ----------------
// grid (NN, 8), block (32, 4): bt = blockIdx.y*4 + threadIdx.y = t*NB + b
__global__ void k_aggx(const float* __restrict__ x) {
    int node = blockIdx.x;
    int bt = blockIdx.y * 4 + threadIdx.y;   // 0..31
    int t = bt >> 1, b = bt & 1;
    int tx = threadIdx.x;                    // feature/4 (0..31)
    const float* vi = x + ((size_t)(b * NT + t) * NN) * NIN;
    float di = g_dinv[node];
    float4 acc = *(const float4*)(vi + (size_t)node * NIN + tx * 4);
    float sw = di * di;
    acc.x *= sw; acc.y *= sw; acc.z *= sw; acc.w *= sw;
    int beg = g_rowptr[node], end = g_rowptr[node + 1];
    int j = beg;
    for (; j + 1 < end; j += 2) {
        float w0 = g_wedge[j],     w1 = g_wedge[j + 1];
        int   c0 = g_col[j],       c1 = g_col[j + 1];
        float4 v0 = *(const float4*)(vi + (size_t)c0 * NIN + tx * 4);
        float4 v1 = *(const float4*)(vi + (size_t)c1 * NIN + tx * 4);
        acc.x += w0 * v0.x + w1 * v1.x; acc.y += w0 * v0.y + w1 * v1.y;
        acc.z += w0 * v0.z + w1 * v1.z; acc.w += w0 * v0.w + w1 * v1.w;
    }
    if (j < end) {
        float w = g_wedge[j]; int c = g_col[j];
        float4 v = *(const float4*)(vi + (size_t)c * NIN + tx * 4);
        acc.x += w * v.x; acc.y += w * v.y; acc.z += w * v.z; acc.w += w * v.w;
    }
    size_t o = ((size_t)bt * NN + node) * NIN + tx * 4;  // = (t*ROWS + b*NN + node)*NIN
    bf16 h0, l0, h1, l1, h2, l2, h3, l3;
    split2(acc.x, h0, l0); split2(acc.y, h1, l1);
    split2(acc.z, h2, l2); split2(acc.w, h3, l3);
    *(ushort4*)(g_AxHi + o) = make_ushort4(__bfloat16_as_ushort(h0), __bfloat16_as_ushort(h1),
                                           __bfloat16_as_ushort(h2), __bfloat16_as_ushort(h3));
    *(ushort4*)(g_AxLo + o) = make_ushort4(__bfloat16_as_ushort(l0), __bfloat16_as_ushort(l1),
                                           __bfloat16_as_ushort(l2), __bfloat16_as_ushort(l3));
}

// ---------------- agg(h) per step ----------------
// grid NN, block (64, 2)
__global__ void k_aggh() {
    int node = blockIdx.x;
    int b    = threadIdx.y;
    int tx   = threadIdx.x;          // 0..63
    const float* vi = g_h + (size_t)b * NN * NHID;
    float di = g_dinv[node];
    float4 acc = *(const float4*)(vi + (size_t)node * NHID + tx * 4);
    float sw = di * di;
    acc.x *= sw; acc.y *= sw; acc.z *= sw; acc.w *= sw;
    int beg = g_rowptr[node], end = g_rowptr[node + 1];
    int j = beg;
    for (; j + 1 < end; j += 2) {
        float w0 = g_wedge[j],     w1 = g_wedge[j + 1];
        int   c0 = g_col[j],       c1 = g_col[j + 1];
        float4 v0 = *(const float4*)(vi + (size_t)c0 * NHID + tx * 4);
        float4 v1 = *(const float4*)(vi + (size_t)c1 * NHID + tx * 4);
        acc.x += w0 * v0.x + w1 * v1.x; acc.y += w0 * v0.y + w1 * v1.y;
        acc.z += w0 * v0.z + w1 * v1.z; acc.w += w0 * v0.w + w1 * v1.w;
    }
    if (j < end) {
        float w = g_wedge[j]; int c = g_col[j];
        float4 v = *(const float4*)(vi + (size_t)c * NHID + tx * 4);
        acc.x += w * v.x; acc.y += w * v.y; acc.z += w * v.z; acc.w += w * v.w;
    }
    size_t o = ((size_t)b * NN + node) * NHID + tx * 4;   // row-major r*256
    bf16 h0, l0, h1, l1, h2, l2, h3, l3;
    split2(acc.x, h0, l0); split2(acc.y, h1, l1);
    split2(acc.z, h2, l2); split2(acc.w, h3, l3);
    *(ushort4*)(g_AhHi + o) = make_ushort4(__bfloat16_as_ushort(h0), __bfloat16_as_ushort(h1),
                                           __bfloat16_as_ushort(h2), __bfloat16_as_ushort(h3));
    *(ushort4*)(g_AhLo + o) = make_ushort4(__bfloat16_as_ushort(l0), __bfloat16_as_ushort(l1),
                                           __bfloat16_as_ushort(l2), __bfloat16_as_ushort(l3));
}

// ---------------- weight packing (transposed + gate-interleaved + split) ----
__global__ void k_pack(const float* __restrict__ Wxr, const float* __restrict__ Whr,
                       const float* __restrict__ Wxz, const float* __restrict__ Whz,
                       const float* __restrict__ Wxn, const float* __restrict__ Whn,
                       const float* __restrict__ bxr, const float* __restrict__ bhr,
                       const float* __restrict__ bxz, const float* __restrict__ bhz,
                       const float* __restrict__ bxn, const float* __restrict__ bhn,
                       const float* __restrict__ Wfc) {
    int idx = blockIdx.x * blockDim.x + threadIdx.x;
    if (idx < GC * KCAT) {
        int cp = idx / KCAT;
        int k  = idx - cp * KCAT;
        int d = cp >> 2, g = cp & 3;
        bool xk = k < 128;
        int kh = k - 128;
        float v;
        if (g == 0)      v = xk ? Wxr[k * 256 + d] : Whr[kh * 256 + d];
        else if (g == 1) v = xk ? Wxz[k * 256 + d] : Whz[kh * 256 + d];
        else if (g == 2) v = xk ? Wxn[k * 256 + d] : 0.0f;
        else             v = xk ? 0.0f : Whn[kh * 256 + d];
        bf16 hi, lo; split2(v, hi, lo);
        g_WThi[idx] = hi; g_WTlo[idx] = lo;
    }
    if (idx < GC) {
        int d = idx >> 2, g = idx & 3;
        float bv;
        if (g == 0)      bv = bxr[d] + bhr[d];
        else if (g == 1) bv = bxz[d] + bhz[d];
        else if (g == 2) bv = bxn[d];
        else             bv = bhn[d];
        g_biasPack[idx] = bv;
    }
    if (idx < NOUT * NHID) {
        int o = idx >> 8;          // NHID = 256
        int k = idx & 255;
        bf16 hi, lo; split2(Wfc[k * NOUT + o], hi, lo);
        g_WfcThi[idx] = hi; g_WfcTlo[idx] = lo;
    }
}

// ---------------- split-bf16 tensor-core GEMM (3-stage pipeline) ----------
// GATES=true: A = [Ax(t) | Ah], K=384 (or 128 at t=0); fused GRU epilogue
//             updating g_h + writing h splits into hist[t].
// GATES=false: A = hist (M=320000, K=256); bias + scatter into out[B,T,N,OUT].

__device__ __forceinline__ uint32_t smem_u32(const void* p) {
    uint32_t a;
    asm("{ .reg .u64 t; cvta.to.shared.u64 t, %1; cvt.u32.u64 %0, t; }"
        : "=r"(a) : "l"(p));
    return a;
}

__device__ __forceinline__ void ldsm4(uint32_t& r0, uint32_t& r1, uint32_t& r2,
                                      uint32_t& r3, uint32_t addr) {
    asm volatile("ldmatrix.sync.aligned.m8n8.x4.shared.b16 {%0,%1,%2,%3}, [%4];"
                 : "=r"(r0), "=r"(r1), "=r"(r2), "=r"(r3) : "r"(addr));
}

__device__ __forceinline__ void mma16(float* c, const uint32_t* a, const uint32_t* b) {
    asm volatile(
        "mma.sync.aligned.m16n8k16.row.col.f32.bf16.bf16.f32 "
        "{%0,%1,%2,%3}, {%4,%5,%6,%7}, {%8,%9}, {%0,%1,%2,%3};"
        : "+f"(c[0]), "+f"(c[1]), "+f"(c[2]), "+f"(c[3])
        : "r"(a[0]), "r"(a[1]), "r"(a[2]), "r"(a[3]), "r"(b[0]), "r"(b[1]));
}

template <bool GATES>
__global__ void __launch_bounds__(256)
k_mma(const bf16* __restrict__ A0hi, const bf16* __restrict__ A0lo,
      const bf16* __restrict__ A1hi, const bf16* __restrict__ A1lo,
      const bf16* __restrict__ Bhi, const bf16* __restrict__ Blo, int ldb,
      float* __restrict__ C, const float* __restrict__ bias,
      int M, int K, int t) {
    // 3 bufs x [plane 4KB: Ahi|Alo|Bhi|Blo], each plane [khalf 2KB][row][16B]
    __shared__ __align__(16) char smem[49152];

    const int tid = threadIdx.x;
    const int lane = tid & 31;
    const int wid = tid >> 5;
    const int wm = wid & 1;          // 2 warps in M
    const int wn = wid >> 1;         // 4 warps in N
    const int m0 = blockIdx.y * BM;
    const int n0 = blockIdx.x * BN;

    const uint32_t sbase = smem_u32(smem);

    // staging: thread -> (row = tid>>1, khalf = tid&1), one 16B chunk per plane
    const int st_row = tid >> 1;
    const int st_kh  = tid & 1;

    // per-thread A source base pointers (fixed row)
    const int r = m0 + st_row;
    const bool rvalid = r < M;
    const int rc = rvalid ? r : 0;
    const bf16 *aXhi, *aXlo, *aHhi, *aHlo;
    if (GATES) {
        size_t xoff = ((size_t)t * ROWS + rc) * NIN + st_kh * 8;
        aXhi = A0hi + xoff; aXlo = A0lo + xoff;
        size_t hoff = (size_t)rc * NHID + st_kh * 8;
        aHhi = A1hi + hoff; aHlo = A1lo + hoff;
    } else {
        size_t off = (size_t)rc * NHID + st_kh * 8;
        aXhi = A0hi + off; aXlo = A0lo + off;
        aHhi = A0hi; aHlo = A0lo;   // unused
    }
    const bf16* bSrcHi = Bhi + (size_t)(n0 + st_row) * ldb + st_kh * 8;
    const bf16* bSrcLo = Blo + (size_t)(n0 + st_row) * ldb + st_kh * 8;
    const int pa = rvalid ? 16 : 0;

    // ldmatrix lane geometry (same formula for A and B)
    const int lrow = lane & 15;
    const int lkh  = lane >> 4;

    float acc[4][4][4];
#pragma unroll
    for (int i = 0; i < 4; i++)
#pragma unroll
        for (int j = 0; j < 4; j++)
#pragma unroll
            for (int q = 0; q < 4; q++) acc[i][j][q] = 0.0f;

    const int KT = K / BK;

    auto stage = [&](int buf, int k0) {
        uint32_t base = sbase + (uint32_t)buf * 16384u;
        uint32_t off = (uint32_t)(st_kh * 2048 + st_row * 16);
        const bf16 *sa_hi, *sa_lo;
        if (GATES && k0 >= NIN) { sa_hi = aHhi + (k0 - NIN); sa_lo = aHlo + (k0 - NIN); }
        else                    { sa_hi = aXhi + k0;         sa_lo = aXlo + k0; }
        asm volatile("cp.async.ca.shared.global [%0], [%1], 16, %2;"
                     :: "r"(base + off), "l"(sa_hi), "r"(pa));
        asm volatile("cp.async.ca.shared.global [%0], [%1], 16, %2;"
                     :: "r"(base + 4096u + off), "l"(sa_lo), "r"(pa));
        asm volatile("cp.async.ca.shared.global [%0], [%1], 16, %2;"
                     :: "r"(base + 8192u + off), "l"(bSrcHi + k0), "r"(16));
        asm volatile("cp.async.ca.shared.global [%0], [%1], 16, %2;"
                     :: "r"(base + 12288u + off), "l"(bSrcLo + k0), "r"(16));
    };

    stage(0, 0);
    asm volatile("cp.async.commit_group;");
    stage(1, BK);
    asm volatile("cp.async.commit_group;");

    for (int kt = 0; kt < KT; kt++) {
        if (kt + 2 < KT) {
            stage((kt + 2) % 3, (kt + 2) * BK);
            asm volatile("cp.async.commit_group;");
            asm volatile("cp.async.wait_group 2;");
        } else if (kt + 1 < KT) {
            asm volatile("cp.async.wait_group 1;");
        } else {
            asm volatile("cp.async.wait_group 0;");
        }
        __syncthreads();

        const uint32_t pA  = sbase + (uint32_t)(kt % 3) * 16384u;
        const uint32_t pA2 = pA + 4096u;
        const uint32_t pB  = pA + 8192u;
        const uint32_t pB2 = pA + 12288u;
        const uint32_t loff = (uint32_t)(lkh * 2048);

        uint32_t ah[4][4], al[4][4], bh[4][2], bl[4][2];
#pragma unroll
        for (int mt = 0; mt < 4; mt++) {
            uint32_t ro = (uint32_t)((wm * 64 + mt * 16 + lrow) * 16);
            ldsm4(ah[mt][0], ah[mt][1], ah[mt][2], ah[mt][3], pA + loff + ro);
            ldsm4(al[mt][0], al[mt][1], al[mt][2], al[mt][3], pA2 + loff + ro);
        }
#pragma unroll
        for (int j = 0; j < 2; j++) {
            uint32_t ro = (uint32_t)((wn * 32 + j * 16 + lrow) * 16);
            uint32_t r0, r1, r2, r3;
            ldsm4(r0, r1, r2, r3, pB + loff + ro);
            bh[2*j][0] = r0; bh[2*j][1] = r2;
            bh[2*j+1][0] = r1; bh[2*j+1][1] = r3;
            ldsm4(r0, r1, r2, r3, pB2 + loff + ro);
            bl[2*j][0] = r0; bl[2*j][1] = r2;
            bl[2*j+1][0] = r1; bl[2*j+1][1] = r3;
        }
#pragma unroll
        for (int mt = 0; mt < 4; mt++)
#pragma unroll
            for (int nt = 0; nt < 4; nt++) {
                mma16(acc[mt][nt], ah[mt], bh[nt]);
                mma16(acc[mt][nt], ah[mt], bl[nt]);
                mma16(acc[mt][nt], al[mt], bh[nt]);
            }
        __syncthreads();
    }

    // ---- epilogue ----
    const int gid = lane >> 2, tg = lane & 3;

    if (GATES) {
        const bool odd = lane & 1;
#pragma unroll
        for (int mt = 0; mt < 4; mt++) {
            int rowb = m0 + wm * 64 + mt * 16;
#pragma unroll
            for (int nt = 0; nt < 4; nt++) {
                float c0 = acc[mt][nt][0], c1 = acc[mt][nt][1];
                float c2 = acc[mt][nt][2], c3 = acc[mt][nt][3];
                float e0 = __shfl_xor_sync(0xffffffffu, c0, 1);
                float e1 = __shfl_xor_sync(0xffffffffu, c1, 1);
                float e2 = __shfl_xor_sync(0xffffffffu, c2, 1);
                float e3 = __shfl_xor_sync(0xffffffffu, c3, 1);
                float v0, v1, v2, v3;
                int row;
                if (!odd) { v0 = c0; v1 = c1; v2 = e0; v3 = e1; row = rowb + gid; }
                else      { v0 = e2; v1 = e3; v2 = c2; v3 = c3; row = rowb + gid + 8; }
                int d = ((n0 + wn * 32 + nt * 8) >> 2) + (tg >> 1);
                if (row < M) {
                    float4 bb = *(const float4*)&bias[4 * d];
                    float rg = 1.0f / (1.0f + __expf(-(v0 + bb.x)));
                    float zg = 1.0f / (1.0f + __expf(-(v1 + bb.y)));
                    float ng = tanhf(v2 + bb.z + rg * (v3 + bb.w));
                    size_t hoff = (size_t)row * NHID + d;
                    float h = g_h[hoff];
                    float hn2 = h + zg * (ng - h);
                    g_h[hoff] = hn2;
                    bf16 hi, lo; split2(hn2, hi, lo);
                    size_t hist = ((size_t)t * ROWS + row) * NHID + d;
                    g_histHi[hist] = hi;
                    g_histLo[hist] = lo;
                }
            }
        }
    } else {
#pragma unroll
        for (int mt = 0; mt < 4; mt++) {
            int r0 = m0 + wm * 64 + mt * 16 + gid;
            int r1 = r0 + 8;
            // decompose r = t*ROWS + b*NN + node -> out[((b*NT+t)*NN+node)*NOUT]
            int t0 = r0 / ROWS, rm0 = r0 - t0 * ROWS;
            int b0 = rm0 / NN,  nd0 = rm0 - b0 * NN;
            int t1 = r1 / ROWS, rm1 = r1 - t1 * ROWS;
            int b1 = rm1 / NN,  nd1 = rm1 - b1 * NN;
            size_t base0 = (((size_t)b0 * NT + t0) * NN + nd0) * NOUT;
            size_t base1 = (((size_t)b1 * NT + t1) * NN + nd1) * NOUT;
#pragma unroll
            for (int nt = 0; nt < 4; nt++) {
                int col = n0 + wn * 32 + nt * 8 + tg * 2;
                float bx = bias[col], by = bias[col + 1];
                float2 o0 = make_float2(acc[mt][nt][0] + bx, acc[mt][nt][1] + by);
                *(float2*)&C[base0 + col] = o0;
                float2 o1 = make_float2(acc[mt][nt][2] + bx, acc[mt][nt][3] + by);
                *(float2*)&C[base1 + col] = o1;
            }
        }
    }
}

// ---------------- launcher ----------------
extern "C" void kernel_launch(void* const* d_in, const int* in_sizes, int n_in,
                              void* d_out, int out_size) {
    (void)in_sizes; (void)n_in; (void)out_size;
    const float* x   = (const float*)d_in[0];
    const int*   ei  = (const int*)d_in[1];
    const float* Wxr = (const float*)d_in[2];  const float* bxr = (const float*)d_in[3];
    const float* Whr = (const float*)d_in[4];  const float* bhr = (const float*)d_in[5];
    const float* Wxz = (const float*)d_in[6];  const float* bxz = (const float*)d_in[7];
    const float* Whz = (const float*)d_in[8];  const float* bhz = (const float*)d_in[9];
    const float* Wxn = (const float*)d_in[10]; const float* bxn = (const float*)d_in[11];
    const float* Whn = (const float*)d_in[12]; const float* bhn = (const float*)d_in[13];
    const float* Wfc = (const float*)d_in[14]; const float* bfc = (const float*)d_in[15];
    float* out = (float*)d_out;

    bf16 *pAxHi, *pAxLo, *pAhHi, *pAhLo, *pHistHi, *pHistLo;
    bf16 *pWThi, *pWTlo, *pWfcThi, *pWfcTlo;
    float *pbias;
    cudaGetSymbolAddress((void**)&pAxHi,   g_AxHi);
    cudaGetSymbolAddress((void**)&pAxLo,   g_AxLo);
    cudaGetSymbolAddress((void**)&pAhHi,   g_AhHi);
    cudaGetSymbolAddress((void**)&pAhLo,   g_AhLo);
    cudaGetSymbolAddress((void**)&pHistHi, g_histHi);
    cudaGetSymbolAddress((void**)&pHistLo, g_histLo);
    cudaGetSymbolAddress((void**)&pWThi,   g_WThi);
    cudaGetSymbolAddress((void**)&pWTlo,   g_WTlo);
    cudaGetSymbolAddress((void**)&pWfcThi, g_WfcThi);
    cudaGetSymbolAddress((void**)&pWfcTlo, g_WfcTlo);
    cudaGetSymbolAddress((void**)&pbias,   g_biasPack);

    // setup
    k_zero_all<<<592, 256>>>();
    k_count<<<(NE + 255) / 256, 256>>>(ei);
    k_scan_all<<<1, 1024>>>(ei);
    k_aggx<<<dim3(NN, 8), dim3(32, 4)>>>(x);
    k_pack<<<(GC * KCAT + 255) / 256, 256>>>(Wxr, Whr, Wxz, Whz, Wxn, Whn,
                                             bxr, bhr, bxz, bhz, bxn, bhn, Wfc);

    dim3 gateGrid(GC / BN, (ROWS + BM - 1) / BM);    // 8 x 157

    for (int t = 0; t < NT; t++) {
        if (t > 0) k_aggh<<<NN, dim3(64, 2)>>>();
        int K = (t == 0) ? NIN : KCAT;   // h=0 at t=0: skip h-side K entirely
        k_mma<true><<<gateGrid, 256>>>(pAxHi, pAxLo, pAhHi, pAhLo,
                                       pWThi, pWTlo, KCAT,
                                       nullptr, pbias, ROWS, K, t);
    }

    // one big FC GEMM over all timesteps: M=320000, K=256, N=128
    dim3 fcGrid(NOUT / BN, HISTROWS / BM);           // 1 x 2500
    k_mma<false><<<fcGrid, 256>>>(pHistHi, pHistLo, nullptr, nullptr,
                                  pWfcThi, pWfcTlo, NHID,
                                  out, bfc, HISTROWS, NHID, 0);
}